// round 5
// baseline (speedup 1.0000x reference)
#include <cuda_runtime.h>
#include <cuda_bf16.h>
#include <math.h>
#include <stdint.h>

#define N_ 2048
#define D_ 512
#define K_ 65536

constexpr float TEMP_INV = 5.0f;
constexpr float CSHIFT   = 5.0f;
constexpr float EPS      = 1e-8f;

// ---------------- device scratch (allocation-free rule) ----------------
__device__ float g_inv_qn[N_];
__device__ float g_lpos[N_];
__device__ float g_S[N_];
__device__ __nv_bfloat16 g_Qn[N_ * D_];   // 2 MB  (query * 5*inv_qn)
__device__ __nv_bfloat16 g_Un[K_ * D_];   // 64 MB (queue * inv_un)

// ---------------- PTX helpers ----------------
__device__ __forceinline__ uint32_t smem_u32(const void* p) {
    uint32_t a;
    asm("{ .reg .u64 t; cvta.to.shared.u64 t, %1; cvt.u32.u64 %0, t; }" : "=r"(a) : "l"(p));
    return a;
}

#define CP_ASYNC16(dst, src) \
    asm volatile("cp.async.cg.shared.global [%0], [%1], 16;\n" :: "r"(dst), "l"(src))
#define CP_COMMIT() asm volatile("cp.async.commit_group;\n" ::: "memory")
#define CP_WAIT(n)  asm volatile("cp.async.wait_group %0;\n" :: "n"(n) : "memory")

#define LDSM4(R0, R1, R2, R3, addr) \
    asm volatile("ldmatrix.sync.aligned.m8n8.x4.shared.b16 {%0,%1,%2,%3}, [%4];" \
        : "=r"(R0), "=r"(R1), "=r"(R2), "=r"(R3) : "r"(addr))

#define MMA16816(D, A, B0, B1) \
    asm volatile("mma.sync.aligned.m16n8k16.row.col.f32.bf16.bf16.f32 " \
        "{%0,%1,%2,%3}, {%4,%5,%6,%7}, {%8,%9}, {%0,%1,%2,%3};" \
        : "+f"((D)[0]), "+f"((D)[1]), "+f"((D)[2]), "+f"((D)[3]) \
        : "r"((A)[0]), "r"((A)[1]), "r"((A)[2]), "r"((A)[3]), "r"(B0), "r"(B1))

__device__ __forceinline__ float warp_sum(float v) {
#pragma unroll
    for (int o = 16; o > 0; o >>= 1) v += __shfl_xor_sync(0xffffffffu, v, o);
    return v;
}

// ---------------------------------------------------------------------------
// Prep 1: q/k norms, l_pos, seed g_S, write Qn = bf16(q * 5*inv_qn)
// ---------------------------------------------------------------------------
__global__ void prep_qk(const float* __restrict__ q, const float* __restrict__ k) {
    int n = blockIdx.x;
    int tid = threadIdx.x;  // 128
    float4 a = ((const float4*)(q + (size_t)n * D_))[tid];
    float4 b = ((const float4*)(k + (size_t)n * D_))[tid];
    float sq = a.x * a.x + a.y * a.y + a.z * a.z + a.w * a.w;
    float sk = b.x * b.x + b.y * b.y + b.z * b.z + b.w * b.w;
    float dp = a.x * b.x + a.y * b.y + a.z * b.z + a.w * b.w;

    __shared__ float s_sq[4], s_sk[4], s_dp[4];
    __shared__ float s_scale;
    sq = warp_sum(sq); sk = warp_sum(sk); dp = warp_sum(dp);
    int wid = tid >> 5, lid = tid & 31;
    if (lid == 0) { s_sq[wid] = sq; s_sk[wid] = sk; s_dp[wid] = dp; }
    __syncthreads();
    if (tid == 0) {
        float tsq = s_sq[0] + s_sq[1] + s_sq[2] + s_sq[3];
        float tsk = s_sk[0] + s_sk[1] + s_sk[2] + s_sk[3];
        float tdp = s_dp[0] + s_dp[1] + s_dp[2] + s_dp[3];
        float qn = sqrtf(tsq), kn = sqrtf(tsk);
        float lpos = tdp / fmaxf(qn * kn, EPS) * TEMP_INV;
        g_lpos[n] = lpos;
        g_inv_qn[n] = 1.0f / qn;
        g_S[n] = expf(lpos - CSHIFT);
        s_scale = TEMP_INV / qn;
    }
    __syncthreads();
    float s = s_scale;
    __nv_bfloat162 lo = __floats2bfloat162_rn(a.x * s, a.y * s);
    __nv_bfloat162 hi = __floats2bfloat162_rn(a.z * s, a.w * s);
    uint2 pk = make_uint2(*(uint32_t*)&lo, *(uint32_t*)&hi);
    ((uint2*)(g_Qn + (size_t)n * D_))[tid] = pk;
}

// ---------------------------------------------------------------------------
// Prep 2: queue norms, write Un = bf16(u * inv_un)
// ---------------------------------------------------------------------------
__global__ void prep_queue(const float* __restrict__ u) {
    int r = blockIdx.x;
    int tid = threadIdx.x;  // 128
    float4 a = ((const float4*)(u + (size_t)r * D_))[tid];
    float s = a.x * a.x + a.y * a.y + a.z * a.z + a.w * a.w;
    __shared__ float sm[4];
    __shared__ float s_scale;
    s = warp_sum(s);
    int wid = tid >> 5, lid = tid & 31;
    if (lid == 0) sm[wid] = s;
    __syncthreads();
    if (tid == 0) s_scale = rsqrtf(sm[0] + sm[1] + sm[2] + sm[3]);
    __syncthreads();
    float sc = s_scale;
    __nv_bfloat162 lo = __floats2bfloat162_rn(a.x * sc, a.y * sc);
    __nv_bfloat162 hi = __floats2bfloat162_rn(a.z * sc, a.w * sc);
    uint2 pk = make_uint2(*(uint32_t*)&lo, *(uint32_t*)&hi);
    ((uint2*)(g_Un + (size_t)r * D_))[tid] = pk;
}

// ---------------------------------------------------------------------------
// Main GEMM+LSE via mma.sync.m16n8k16 (bf16 -> fp32).
// CTA tile: 256 queue rows (M) x 128 query rows (N), BK=32, 3-stage cp.async.
// Warp layout 4(M) x 2(N), warp tile 64x64 -> 32 MMA : 8 LDSM.x4 per k16.
// Smem rows padded to 80B (stride 80 -> conflict-free ldmatrix).
// Epilogue: exp(l-5) in regs, butterfly reduce over M rows, atomicAdd(g_S).
// ---------------------------------------------------------------------------
constexpr int BM = 256, BN = 128, BK = 32;
constexpr uint32_t ROWB = 80;                    // 32 bf16 = 64B + 16B pad
constexpr uint32_t A_BYTES = 256 * ROWB;         // 20480
constexpr uint32_t B_BYTES = 128 * ROWB;         // 10240
constexpr uint32_t STAGE_BYTES = A_BYTES + B_BYTES;  // 30720
constexpr uint32_t SMEM_TOTAL = 3 * STAGE_BYTES;     // 92160
constexpr int NIT = D_ / BK;                     // 16

__device__ __forceinline__ void load_stage(uint32_t sb, int st, int m0, int n0,
                                           int kk, int tid) {
    uint32_t base = sb + st * STAGE_BYTES;
#pragma unroll
    for (int i = 0; i < 6; i++) {
        int id = tid + i * 256;          // 0..1535 : first 1024 = A, rest = B
        int isB = (id >= 1024);
        int l2 = id - (isB ? 1024 : 0);
        int row = l2 >> 2, c = l2 & 3;   // A row 0..255 / B row 0..127, 16B chunk
        const __nv_bfloat16* src =
            (isB ? g_Qn + (size_t)(n0 + row) * D_ : g_Un + (size_t)(m0 + row) * D_)
            + kk + c * 8;
        uint32_t dst = base + (isB ? A_BYTES : 0u) + row * ROWB + c * 16u;
        CP_ASYNC16(dst, src);
    }
}

__global__ __launch_bounds__(256, 1) void gemm_lse_mma() {
    extern __shared__ __align__(128) char smem[];
    const uint32_t sb = smem_u32(smem);
    const int tid = threadIdx.x;
    const int wid = tid >> 5, lane = tid & 31;
    const int n0 = blockIdx.x * BN;      // query tile (fast -> Un shared via L2)
    const int m0 = blockIdx.y * BM;      // queue tile
    const int warp_m = wid & 3;          // 0..3 -> 64 rows each
    const int warp_n = wid >> 2;         // 0..1 -> 64 cols each

    float acc[4][8][4];                  // [m16 tile][n8 tile][frag]
#pragma unroll
    for (int i = 0; i < 4; i++)
#pragma unroll
        for (int j = 0; j < 8; j++)
#pragma unroll
            for (int r = 0; r < 4; r++) acc[i][j][r] = 0.0f;

    load_stage(sb, 0, m0, n0, 0, tid);  CP_COMMIT();
    load_stage(sb, 1, m0, n0, BK, tid); CP_COMMIT();

    const uint32_t aOff = (warp_m * 64 + (lane & 15)) * ROWB + ((lane >> 4) * 16);
    const uint32_t bOff = A_BYTES + (warp_n * 64 + (lane & 15)) * ROWB + ((lane >> 4) * 16);

    for (int it = 0; it < NIT; it++) {
        if (it == NIT - 1) { CP_WAIT(0); } else { CP_WAIT(1); }
        __syncthreads();
        if (it + 2 < NIT) {              // prefetch before compute: full 2-stage overlap
            load_stage(sb, (it + 2) % 3, m0, n0, (it + 2) * BK, tid);
            CP_COMMIT();
        }
        const uint32_t stb = sb + (it % 3) * STAGE_BYTES;
#pragma unroll
        for (int ks = 0; ks < 2; ks++) {      // two k16 steps per BK=32
            uint32_t a[4][4], b[4][4];
#pragma unroll
            for (int mt = 0; mt < 4; mt++)
                LDSM4(a[mt][0], a[mt][1], a[mt][2], a[mt][3],
                      stb + aOff + mt * 16 * ROWB + ks * 32);
#pragma unroll
            for (int ng = 0; ng < 4; ng++)
                LDSM4(b[ng][0], b[ng][1], b[ng][2], b[ng][3],
                      stb + bOff + ng * 16 * ROWB + ks * 32);
#pragma unroll
            for (int mt = 0; mt < 4; mt++) {
#pragma unroll
                for (int ng = 0; ng < 4; ng++) {
                    MMA16816(acc[mt][2 * ng + 0], a[mt], b[ng][0], b[ng][2]);
                    MMA16816(acc[mt][2 * ng + 1], a[mt], b[ng][1], b[ng][3]);
                }
            }
        }
    }

    // Epilogue: exp -> reduce over 64 warp rows -> atomics (2 cols per lane 0-3)
#pragma unroll
    for (int j = 0; j < 8; j++) {             // n8 tiles
        float s0 = 0.0f, s1 = 0.0f;
#pragma unroll
        for (int mt = 0; mt < 4; mt++) {
            s0 += __expf(acc[mt][j][0] - CSHIFT) + __expf(acc[mt][j][2] - CSHIFT);
            s1 += __expf(acc[mt][j][1] - CSHIFT) + __expf(acc[mt][j][3] - CSHIFT);
        }
#pragma unroll
        for (int o = 4; o <= 16; o <<= 1) {   // reduce over row groups (lane bits 2..4)
            s0 += __shfl_xor_sync(0xffffffffu, s0, o);
            s1 += __shfl_xor_sync(0xffffffffu, s1, o);
        }
        if (lane < 4) {
            int col = n0 + warp_n * 64 + (j >> 1) * 16 + (j & 1) * 8 + lane * 2;
            atomicAdd(&g_S[col], s0);
            atomicAdd(&g_S[col + 1], s1);
        }
    }
}

// ---------------------------------------------------------------------------
// Finalize: loss = mean(C + log(S_n) - lpos_n)
// ---------------------------------------------------------------------------
__global__ void finalize(float* __restrict__ out) {
    int tid = threadIdx.x;  // 1024
    float local = 0.0f;
    for (int n = tid; n < N_; n += 1024)
        local += CSHIFT + logf(g_S[n]) - g_lpos[n];
    __shared__ float red[1024];
    red[tid] = local;
    __syncthreads();
    for (int s = 512; s > 0; s >>= 1) {
        if (tid < s) red[tid] += red[tid + s];
        __syncthreads();
    }
    if (tid == 0) out[0] = red[0] / (float)N_;
}

extern "C" void kernel_launch(void* const* d_in, const int* in_sizes, int n_in,
                              void* d_out, int out_size) {
    const float* query = (const float*)d_in[0];
    const float* keys  = (const float*)d_in[1];
    const float* queue = (const float*)d_in[2];
    float* out = (float*)d_out;

    cudaFuncSetAttribute(gemm_lse_mma, cudaFuncAttributeMaxDynamicSharedMemorySize, SMEM_TOTAL);

    prep_qk<<<N_, 128>>>(query, keys);
    prep_queue<<<K_, 128>>>(queue);
    dim3 grid(N_ / BN, K_ / BM);   // 16 x 256, x fast -> Un tiles shared in L2
    gemm_lse_mma<<<grid, 256, SMEM_TOTAL>>>();
    finalize<<<1, 1024>>>(out);
}

// round 6
// speedup vs baseline: 1.1851x; 1.1851x over previous
#include <cuda_runtime.h>
#include <cuda_bf16.h>
#include <math.h>
#include <stdint.h>

#define N_ 2048
#define D_ 512
#define K_ 65536

constexpr float TEMP_INV = 5.0f;
constexpr float CSHIFT   = 5.0f;
constexpr float EPS      = 1e-8f;
constexpr float QSCALE   = 16.0f;            // extra scale on q-hat (x5 temp folded too)
constexpr float USCALE   = 16.0f;            // extra scale on u-hat
constexpr float INV_SCALE = 1.0f / (16.0f * 16.0f);   // acc -> logit

// ---------------- device scratch (allocation-free rule) ----------------
__device__ float g_lpos[N_];
__device__ float g_S[N_];
__device__ unsigned g_cnt;
__device__ uint32_t g_Q8[N_ * D_ / 4];   // 1 MB  e4m3(80 * q/||q||)
__device__ uint32_t g_U8[K_ * D_ / 4];   // 32 MB e4m3(16 * u/||u||)

// ---------------- PTX helpers ----------------
__device__ __forceinline__ uint32_t smem_u32(const void* p) {
    uint32_t a;
    asm("{ .reg .u64 t; cvta.to.shared.u64 t, %1; cvt.u32.u64 %0, t; }" : "=r"(a) : "l"(p));
    return a;
}

#define CP_ASYNC16(dst, src) \
    asm volatile("cp.async.cg.shared.global [%0], [%1], 16;\n" :: "r"(dst), "l"(src))
#define CP_COMMIT() asm volatile("cp.async.commit_group;\n" ::: "memory")
#define CP_WAIT(n)  asm volatile("cp.async.wait_group %0;\n" :: "n"(n) : "memory")

#define LDSM4(R0, R1, R2, R3, addr) \
    asm volatile("ldmatrix.sync.aligned.m8n8.x4.shared.b16 {%0,%1,%2,%3}, [%4];" \
        : "=r"(R0), "=r"(R1), "=r"(R2), "=r"(R3) : "r"(addr))

// fp8 e4m3 MMA, fp32 accumulate. Fragments = bf16 m16n8k16 layout with each
// b16 slot holding 2 consecutive-k e4m3 -> ldmatrix.b16 works unchanged.
#define MMAFP8(D, A, B0, B1) \
    asm volatile("mma.sync.aligned.m16n8k32.row.col.f32.e4m3.e4m3.f32 " \
        "{%0,%1,%2,%3}, {%4,%5,%6,%7}, {%8,%9}, {%0,%1,%2,%3};" \
        : "+f"((D)[0]), "+f"((D)[1]), "+f"((D)[2]), "+f"((D)[3]) \
        : "r"((A)[0]), "r"((A)[1]), "r"((A)[2]), "r"((A)[3]), "r"(B0), "r"(B1))

__device__ __forceinline__ float warp_sum(float v) {
#pragma unroll
    for (int o = 16; o > 0; o >>= 1) v += __shfl_xor_sync(0xffffffffu, v, o);
    return v;
}

// pack 4 floats -> 4 e4m3 bytes (little-endian element order)
__device__ __forceinline__ uint32_t pack_e4m3x4(float e0, float e1, float e2, float e3) {
    uint16_t lo, hi;
    asm("cvt.rn.satfinite.e4m3x2.f32 %0, %1, %2;" : "=h"(lo) : "f"(e1), "f"(e0));
    asm("cvt.rn.satfinite.e4m3x2.f32 %0, %1, %2;" : "=h"(hi) : "f"(e3), "f"(e2));
    return (uint32_t)lo | ((uint32_t)hi << 16);
}

// ---------------------------------------------------------------------------
// Merged prep: blocks [0,N_) = query/keys path; blocks [N_, N_+K_) = queue.
// ---------------------------------------------------------------------------
__global__ void prep(const float* __restrict__ q, const float* __restrict__ k,
                     const float* __restrict__ u) {
    int tid = threadIdx.x;  // 128
    int wid = tid >> 5, lid = tid & 31;

    if ((int)blockIdx.x < N_) {
        int n = blockIdx.x;
        if (n == 0 && tid == 0) g_cnt = 0;           // reset CTA counter each replay
        float4 a = ((const float4*)(q + (size_t)n * D_))[tid];
        float4 b = ((const float4*)(k + (size_t)n * D_))[tid];
        float sq = a.x * a.x + a.y * a.y + a.z * a.z + a.w * a.w;
        float sk = b.x * b.x + b.y * b.y + b.z * b.z + b.w * b.w;
        float dp = a.x * b.x + a.y * b.y + a.z * b.z + a.w * b.w;

        __shared__ float s_sq[4], s_sk[4], s_dp[4];
        __shared__ float s_scale;
        sq = warp_sum(sq); sk = warp_sum(sk); dp = warp_sum(dp);
        if (lid == 0) { s_sq[wid] = sq; s_sk[wid] = sk; s_dp[wid] = dp; }
        __syncthreads();
        if (tid == 0) {
            float tsq = s_sq[0] + s_sq[1] + s_sq[2] + s_sq[3];
            float tsk = s_sk[0] + s_sk[1] + s_sk[2] + s_sk[3];
            float tdp = s_dp[0] + s_dp[1] + s_dp[2] + s_dp[3];
            float qn = sqrtf(tsq), kn = sqrtf(tsk);
            float lpos = tdp / fmaxf(qn * kn, EPS) * TEMP_INV;
            g_lpos[n] = lpos;
            g_S[n] = expf(lpos - CSHIFT);
            s_scale = TEMP_INV * QSCALE / qn;        // 80 / ||q||
        }
        __syncthreads();
        float s = s_scale;
        g_Q8[(size_t)n * 128 + tid] = pack_e4m3x4(a.x * s, a.y * s, a.z * s, a.w * s);
    } else {
        int r = blockIdx.x - N_;
        float4 a = ((const float4*)(u + (size_t)r * D_))[tid];
        float s = a.x * a.x + a.y * a.y + a.z * a.z + a.w * a.w;
        __shared__ float sm[4];
        __shared__ float s_scale;
        s = warp_sum(s);
        if (lid == 0) sm[wid] = s;
        __syncthreads();
        if (tid == 0) s_scale = USCALE * rsqrtf(sm[0] + sm[1] + sm[2] + sm[3]);
        __syncthreads();
        float sc = s_scale;
        g_U8[(size_t)r * 128 + tid] = pack_e4m3x4(a.x * sc, a.y * sc, a.z * sc, a.w * sc);
    }
}

// ---------------------------------------------------------------------------
// GEMM+LSE via fp8 mma.m16n8k32 (e4m3 -> fp32).
// CTA tile: 128 queue rows (M) x 128 query rows (N), BK=64 fp8 (64B rows),
// 3-stage cp.async, warps 2(M) x 4(N), warp tile 64x32.
// Smem rows padded to 80B -> conflict-free ldmatrix.
// Fused finalize via atomic CTA counter.
// ---------------------------------------------------------------------------
constexpr int BM = 128, BN = 128, BK = 64;
constexpr uint32_t ROWB = 80;                    // 64B fp8 + 16B pad
constexpr uint32_t A_BYTES = 128 * ROWB;         // 10240
constexpr uint32_t STAGE_BYTES = 2 * A_BYTES;    // 20480
constexpr uint32_t SMEM_TOTAL = 3 * STAGE_BYTES; // 61440
constexpr int NIT = D_ / BK;                     // 8
constexpr int TOTAL_CTAS = (N_ / BN) * (K_ / BM);   // 8192

__device__ __forceinline__ void load_stage(uint32_t sb, int st, int m0, int n0,
                                           int kk, int tid) {
    uint32_t base = sb + st * STAGE_BYTES;
    const uint8_t* Q8 = (const uint8_t*)g_Q8;
    const uint8_t* U8 = (const uint8_t*)g_U8;
#pragma unroll
    for (int i = 0; i < 4; i++) {
        int id = tid + i * 256;          // 0..1023 : first 512 = A(U8), rest = B(Q8)
        int isB = (id >= 512);
        int l2 = id & 511;
        int row = l2 >> 2, c = l2 & 3;   // row 0..127, 16B chunk 0..3
        const uint8_t* src =
            (isB ? Q8 + (size_t)(n0 + row) * D_ : U8 + (size_t)(m0 + row) * D_)
            + kk + c * 16;
        uint32_t dst = base + (isB ? A_BYTES : 0u) + row * ROWB + c * 16u;
        CP_ASYNC16(dst, src);
    }
}

__global__ __launch_bounds__(256, 2) void gemm_lse_fp8(float* __restrict__ out) {
    extern __shared__ __align__(128) char smem[];
    const uint32_t sb = smem_u32(smem);
    const int tid = threadIdx.x;
    const int wid = tid >> 5, lane = tid & 31;
    const int n0 = blockIdx.x * BN;      // query tile (fast -> U8 shared via L2)
    const int m0 = blockIdx.y * BM;      // queue tile
    const int warp_m = wid & 1;          // 0..1 -> 64 rows
    const int warp_n = wid >> 1;         // 0..3 -> 32 cols

    float acc[4][4][4];
#pragma unroll
    for (int i = 0; i < 4; i++)
#pragma unroll
        for (int j = 0; j < 4; j++)
#pragma unroll
            for (int r = 0; r < 4; r++) acc[i][j][r] = 0.0f;

    load_stage(sb, 0, m0, n0, 0, tid);  CP_COMMIT();
    load_stage(sb, 1, m0, n0, BK, tid); CP_COMMIT();

    const uint32_t aOff = (warp_m * 64 + (lane & 15)) * ROWB + ((lane >> 4) * 16);
    const uint32_t bOff = A_BYTES + (warp_n * 32 + (lane & 15)) * ROWB + ((lane >> 4) * 16);

    for (int it = 0; it < NIT; it++) {
        if (it == NIT - 1) { CP_WAIT(0); } else { CP_WAIT(1); }
        __syncthreads();
        if (it + 2 < NIT) {
            load_stage(sb, (it + 2) % 3, m0, n0, (it + 2) * BK, tid);
            CP_COMMIT();
        }
        const uint32_t stb = sb + (it % 3) * STAGE_BYTES;
#pragma unroll
        for (int ks = 0; ks < 2; ks++) {      // two k32 steps per BK=64
            uint32_t a[4][4], b[2][4];
#pragma unroll
            for (int mt = 0; mt < 4; mt++)
                LDSM4(a[mt][0], a[mt][1], a[mt][2], a[mt][3],
                      stb + aOff + mt * 16 * ROWB + ks * 32);
#pragma unroll
            for (int ng = 0; ng < 2; ng++)
                LDSM4(b[ng][0], b[ng][1], b[ng][2], b[ng][3],
                      stb + bOff + ng * 16 * ROWB + ks * 32);
#pragma unroll
            for (int mt = 0; mt < 4; mt++) {
#pragma unroll
                for (int ng = 0; ng < 2; ng++) {
                    MMAFP8(acc[mt][2 * ng + 0], a[mt], b[ng][0], b[ng][2]);
                    MMAFP8(acc[mt][2 * ng + 1], a[mt], b[ng][1], b[ng][3]);
                }
            }
        }
    }

    // Epilogue: logit = acc/256; exp(l-5); reduce over 64 warp rows; atomics.
#pragma unroll
    for (int j = 0; j < 4; j++) {
        float s0 = 0.0f, s1 = 0.0f;
#pragma unroll
        for (int mt = 0; mt < 4; mt++) {
            s0 += __expf(fmaf(acc[mt][j][0], INV_SCALE, -CSHIFT))
                + __expf(fmaf(acc[mt][j][2], INV_SCALE, -CSHIFT));
            s1 += __expf(fmaf(acc[mt][j][1], INV_SCALE, -CSHIFT))
                + __expf(fmaf(acc[mt][j][3], INV_SCALE, -CSHIFT));
        }
#pragma unroll
        for (int o = 4; o <= 16; o <<= 1) {
            s0 += __shfl_xor_sync(0xffffffffu, s0, o);
            s1 += __shfl_xor_sync(0xffffffffu, s1, o);
        }
        if (lane < 4) {
            int col = n0 + warp_n * 32 + j * 8 + lane * 2;
            atomicAdd(&g_S[col], s0);
            atomicAdd(&g_S[col + 1], s1);
        }
    }

    // Fused finalize: last CTA computes the loss.
    __shared__ bool s_last;
    __threadfence();
    __syncthreads();                       // all warps' atomics fenced before count
    if (tid == 0) s_last = (atomicAdd(&g_cnt, 1u) == TOTAL_CTAS - 1);
    __syncthreads();
    if (s_last) {
        float local = 0.0f;
        for (int n = tid; n < N_; n += 256)
            local += CSHIFT + logf(__ldcg(&g_S[n])) - g_lpos[n];
        __shared__ float red[256];
        red[tid] = local;
        __syncthreads();
        for (int s = 128; s > 0; s >>= 1) {
            if (tid < s) red[tid] += red[tid + s];
            __syncthreads();
        }
        if (tid == 0) out[0] = red[0] / (float)N_;
    }
}

extern "C" void kernel_launch(void* const* d_in, const int* in_sizes, int n_in,
                              void* d_out, int out_size) {
    const float* query = (const float*)d_in[0];
    const float* keys  = (const float*)d_in[1];
    const float* queue = (const float*)d_in[2];
    float* out = (float*)d_out;

    cudaFuncSetAttribute(gemm_lse_fp8, cudaFuncAttributeMaxDynamicSharedMemorySize, SMEM_TOTAL);

    prep<<<N_ + K_, 128>>>(query, keys, queue);
    dim3 grid(N_ / BN, K_ / BM);   // 16 x 512, x fast -> U8 tiles shared in L2
    gemm_lse_fp8<<<grid, 256, SMEM_TOTAL>>>(out);
}

// round 7
// speedup vs baseline: 1.1980x; 1.0108x over previous
#include <cuda_runtime.h>
#include <cuda_bf16.h>
#include <math.h>
#include <stdint.h>

#define N_ 2048
#define D_ 512
#define K_ 65536

constexpr float TEMP_INV = 5.0f;
constexpr float CSHIFT   = 5.0f;
constexpr float EPS      = 1e-8f;
constexpr float QSCALE   = 16.0f;
constexpr float USCALE   = 16.0f;
constexpr float INV_SCALE = 1.0f / (16.0f * 16.0f);

// ---------------- device scratch (allocation-free rule) ----------------
__device__ float g_lpos[N_];
__device__ float g_S[N_];
__device__ unsigned g_cnt;
__device__ uint32_t g_Q8[N_ * D_ / 4];   // 1 MB  e4m3(80 * q/||q||)
__device__ uint32_t g_U8[K_ * D_ / 4];   // 32 MB e4m3(16 * u/||u||)

// ---------------- PTX helpers ----------------
__device__ __forceinline__ uint32_t smem_u32(const void* p) {
    uint32_t a;
    asm("{ .reg .u64 t; cvta.to.shared.u64 t, %1; cvt.u32.u64 %0, t; }" : "=r"(a) : "l"(p));
    return a;
}

#define CP_ASYNC16(dst, src) \
    asm volatile("cp.async.cg.shared.global [%0], [%1], 16;\n" :: "r"(dst), "l"(src))
#define CP_COMMIT() asm volatile("cp.async.commit_group;\n" ::: "memory")
#define CP_WAIT(n)  asm volatile("cp.async.wait_group %0;\n" :: "n"(n) : "memory")

#define LDSM4(R0, R1, R2, R3, addr) \
    asm volatile("ldmatrix.sync.aligned.m8n8.x4.shared.b16 {%0,%1,%2,%3}, [%4];" \
        : "=r"(R0), "=r"(R1), "=r"(R2), "=r"(R3) : "r"(addr))

#define MMAFP8(D, A, B0, B1) \
    asm volatile("mma.sync.aligned.m16n8k32.row.col.f32.e4m3.e4m3.f32 " \
        "{%0,%1,%2,%3}, {%4,%5,%6,%7}, {%8,%9}, {%0,%1,%2,%3};" \
        : "+f"((D)[0]), "+f"((D)[1]), "+f"((D)[2]), "+f"((D)[3]) \
        : "r"((A)[0]), "r"((A)[1]), "r"((A)[2]), "r"((A)[3]), "r"(B0), "r"(B1))

__device__ __forceinline__ float warp_sum(float v) {
#pragma unroll
    for (int o = 16; o > 0; o >>= 1) v += __shfl_xor_sync(0xffffffffu, v, o);
    return v;
}

__device__ __forceinline__ uint32_t pack_e4m3x4(float e0, float e1, float e2, float e3) {
    uint16_t lo, hi;
    asm("cvt.rn.satfinite.e4m3x2.f32 %0, %1, %2;" : "=h"(lo) : "f"(e1), "f"(e0));
    asm("cvt.rn.satfinite.e4m3x2.f32 %0, %1, %2;" : "=h"(hi) : "f"(e3), "f"(e2));
    return (uint32_t)lo | ((uint32_t)hi << 16);
}

// ---------------------------------------------------------------------------
// Merged prep: blocks [0,N_) = query/keys; blocks [N_, N_+K_) = queue.
// ---------------------------------------------------------------------------
__global__ void prep(const float* __restrict__ q, const float* __restrict__ k,
                     const float* __restrict__ u) {
    int tid = threadIdx.x;  // 128
    int wid = tid >> 5, lid = tid & 31;

    if ((int)blockIdx.x < N_) {
        int n = blockIdx.x;
        if (n == 0 && tid == 0) g_cnt = 0;
        float4 a = ((const float4*)(q + (size_t)n * D_))[tid];
        float4 b = ((const float4*)(k + (size_t)n * D_))[tid];
        float sq = a.x * a.x + a.y * a.y + a.z * a.z + a.w * a.w;
        float sk = b.x * b.x + b.y * b.y + b.z * b.z + b.w * b.w;
        float dp = a.x * b.x + a.y * b.y + a.z * b.z + a.w * b.w;

        __shared__ float s_sq[4], s_sk[4], s_dp[4];
        __shared__ float s_scale;
        sq = warp_sum(sq); sk = warp_sum(sk); dp = warp_sum(dp);
        if (lid == 0) { s_sq[wid] = sq; s_sk[wid] = sk; s_dp[wid] = dp; }
        __syncthreads();
        if (tid == 0) {
            float tsq = s_sq[0] + s_sq[1] + s_sq[2] + s_sq[3];
            float tsk = s_sk[0] + s_sk[1] + s_sk[2] + s_sk[3];
            float tdp = s_dp[0] + s_dp[1] + s_dp[2] + s_dp[3];
            float qn = sqrtf(tsq), kn = sqrtf(tsk);
            float lpos = tdp / fmaxf(qn * kn, EPS) * TEMP_INV;
            g_lpos[n] = lpos;
            g_S[n] = expf(lpos - CSHIFT);
            s_scale = TEMP_INV * QSCALE / qn;
        }
        __syncthreads();
        float s = s_scale;
        g_Q8[(size_t)n * 128 + tid] = pack_e4m3x4(a.x * s, a.y * s, a.z * s, a.w * s);
    } else {
        int r = blockIdx.x - N_;
        float4 a = ((const float4*)(u + (size_t)r * D_))[tid];
        float s = a.x * a.x + a.y * a.y + a.z * a.z + a.w * a.w;
        __shared__ float sm[4];
        __shared__ float s_scale;
        s = warp_sum(s);
        if (lid == 0) sm[wid] = s;
        __syncthreads();
        if (tid == 0) s_scale = USCALE * rsqrtf(sm[0] + sm[1] + sm[2] + sm[3]);
        __syncthreads();
        float sc = s_scale;
        g_U8[(size_t)r * 128 + tid] = pack_e4m3x4(a.x * sc, a.y * sc, a.z * sc, a.w * sc);
    }
}

// ---------------------------------------------------------------------------
// GEMM+LSE via fp8 mma.m16n8k32, 4-stage cp.async pipeline (prefetch dist 3,
// wait_group 2 slack).  CTA 128(M,queue) x 128(N,query), BK=64, warps 2Mx4N.
// All cp.async addresses precomputed; advanced by +BK per stage (no IMADs).
// ---------------------------------------------------------------------------
constexpr int BM = 128, BN = 128, BK = 64;
constexpr uint32_t ROWB = 80;
constexpr uint32_t A_BYTES = 128 * ROWB;           // 10240
constexpr uint32_t STAGE_BYTES = 2 * A_BYTES;      // 20480
constexpr int NSTAGE = 4;
constexpr uint32_t SMEM_TOTAL = NSTAGE * STAGE_BYTES;  // 81920
constexpr int NIT = D_ / BK;                       // 8
constexpr int TOTAL_CTAS = (N_ / BN) * (K_ / BM);  // 8192

__global__ __launch_bounds__(256, 2) void gemm_lse_fp8(float* __restrict__ out) {
    extern __shared__ __align__(128) char smem[];
    const uint32_t sb = smem_u32(smem);
    const int tid = threadIdx.x;
    const int wid = tid >> 5, lane = tid & 31;
    const int n0 = blockIdx.x * BN;      // query tile (fast -> U8 shared via L2)
    const int m0 = blockIdx.y * BM;      // queue tile
    const int warp_m = wid & 1;
    const int warp_n = wid >> 1;

    // ---- precompute the 4 cp.async (src ptr, dst offset) pairs ----
    const uint8_t* Q8 = (const uint8_t*)g_Q8;
    const uint8_t* U8 = (const uint8_t*)g_U8;
    const uint8_t* src[4];
    uint32_t dsto[4];
#pragma unroll
    for (int i = 0; i < 4; i++) {
        int id = tid + i * 256;          // 0..1023 : first 512 = A(U8), rest = B(Q8)
        int isB = (id >= 512);
        int l2 = id & 511;
        int row = l2 >> 2, c = l2 & 3;
        src[i] = (isB ? Q8 + (size_t)(n0 + row) * D_ : U8 + (size_t)(m0 + row) * D_)
                 + c * 16;
        dsto[i] = (isB ? A_BYTES : 0u) + row * ROWB + c * 16u;
    }

    float acc[4][4][4];
#pragma unroll
    for (int i = 0; i < 4; i++)
#pragma unroll
        for (int j = 0; j < 4; j++)
#pragma unroll
            for (int r = 0; r < 4; r++) acc[i][j][r] = 0.0f;

    // ---- prologue: fill 3 stages ----
#pragma unroll
    for (int s = 0; s < 3; s++) {
        uint32_t base = sb + s * STAGE_BYTES;
#pragma unroll
        for (int i = 0; i < 4; i++) CP_ASYNC16(base + dsto[i], src[i]);
        CP_COMMIT();
#pragma unroll
        for (int i = 0; i < 4; i++) src[i] += BK;
    }

    const uint32_t aOff = (warp_m * 64 + (lane & 15)) * ROWB + ((lane >> 4) * 16);
    const uint32_t bOff = A_BYTES + (warp_n * 32 + (lane & 15)) * ROWB + ((lane >> 4) * 16);

#pragma unroll
    for (int it = 0; it < NIT; it++) {
        if (it < NIT - 2)      { CP_WAIT(2); }
        else if (it == NIT - 2){ CP_WAIT(1); }
        else                   { CP_WAIT(0); }
        __syncthreads();
        if (it + 3 < NIT) {
            uint32_t base = sb + ((it + 3) & 3) * STAGE_BYTES;
#pragma unroll
            for (int i = 0; i < 4; i++) CP_ASYNC16(base + dsto[i], src[i]);
            CP_COMMIT();
#pragma unroll
            for (int i = 0; i < 4; i++) src[i] += BK;
        }
        const uint32_t stb = sb + (it & 3) * STAGE_BYTES;
#pragma unroll
        for (int ks = 0; ks < 2; ks++) {
            uint32_t a[4][4], b[2][4];
#pragma unroll
            for (int mt = 0; mt < 4; mt++)
                LDSM4(a[mt][0], a[mt][1], a[mt][2], a[mt][3],
                      stb + aOff + mt * 16 * ROWB + ks * 32);
#pragma unroll
            for (int ng = 0; ng < 2; ng++)
                LDSM4(b[ng][0], b[ng][1], b[ng][2], b[ng][3],
                      stb + bOff + ng * 16 * ROWB + ks * 32);
#pragma unroll
            for (int mt = 0; mt < 4; mt++) {
#pragma unroll
                for (int ng = 0; ng < 2; ng++) {
                    MMAFP8(acc[mt][2 * ng + 0], a[mt], b[ng][0], b[ng][2]);
                    MMAFP8(acc[mt][2 * ng + 1], a[mt], b[ng][1], b[ng][3]);
                }
            }
        }
    }

    // Epilogue: logit = acc/256; exp(l-5); reduce over 64 warp rows; atomics.
#pragma unroll
    for (int j = 0; j < 4; j++) {
        float s0 = 0.0f, s1 = 0.0f;
#pragma unroll
        for (int mt = 0; mt < 4; mt++) {
            s0 += __expf(fmaf(acc[mt][j][0], INV_SCALE, -CSHIFT))
                + __expf(fmaf(acc[mt][j][2], INV_SCALE, -CSHIFT));
            s1 += __expf(fmaf(acc[mt][j][1], INV_SCALE, -CSHIFT))
                + __expf(fmaf(acc[mt][j][3], INV_SCALE, -CSHIFT));
        }
#pragma unroll
        for (int o = 4; o <= 16; o <<= 1) {
            s0 += __shfl_xor_sync(0xffffffffu, s0, o);
            s1 += __shfl_xor_sync(0xffffffffu, s1, o);
        }
        if (lane < 4) {
            int col = n0 + warp_n * 32 + j * 8 + lane * 2;
            atomicAdd(&g_S[col], s0);
            atomicAdd(&g_S[col + 1], s1);
        }
    }

    // Fused finalize: last CTA computes the loss.
    __shared__ bool s_last;
    __threadfence();
    __syncthreads();
    if (tid == 0) s_last = (atomicAdd(&g_cnt, 1u) == TOTAL_CTAS - 1);
    __syncthreads();
    if (s_last) {
        float local = 0.0f;
        for (int n = tid; n < N_; n += 256)
            local += CSHIFT + logf(__ldcg(&g_S[n])) - g_lpos[n];
        __shared__ float red[256];
        red[tid] = local;
        __syncthreads();
        for (int s = 128; s > 0; s >>= 1) {
            if (tid < s) red[tid] += red[tid + s];
            __syncthreads();
        }
        if (tid == 0) out[0] = red[0] / (float)N_;
    }
}

extern "C" void kernel_launch(void* const* d_in, const int* in_sizes, int n_in,
                              void* d_out, int out_size) {
    const float* query = (const float*)d_in[0];
    const float* keys  = (const float*)d_in[1];
    const float* queue = (const float*)d_in[2];
    float* out = (float*)d_out;

    cudaFuncSetAttribute(gemm_lse_fp8, cudaFuncAttributeMaxDynamicSharedMemorySize, SMEM_TOTAL);

    prep<<<N_ + K_, 128>>>(query, keys, queue);
    dim3 grid(N_ / BN, K_ / BM);   // 16 x 512, x fast -> U8 tiles shared in L2
    gemm_lse_fp8<<<grid, 256, SMEM_TOTAL>>>(out);
}

// round 8
// speedup vs baseline: 1.2909x; 1.0776x over previous
#include <cuda_runtime.h>
#include <cuda_bf16.h>
#include <cuda_fp16.h>
#include <math.h>
#include <stdint.h>

#define N_ 2048
#define D_ 512
#define K_ 65536

constexpr float TEMP_INV = 5.0f;
constexpr float CSHIFT   = 5.0f;
constexpr float EPS      = 1e-8f;
constexpr float QSCALE   = 16.0f;
constexpr float USCALE   = 16.0f;
constexpr float INV_SCALE = 1.0f / (16.0f * 16.0f);

// ---------------- device scratch (allocation-free rule) ----------------
__device__ float g_lpos[N_];
__device__ float g_S[N_];
__device__ unsigned g_cnt;
__device__ uint32_t g_Q8[N_ * D_ / 4];   // 1 MB  e4m3(80 * q/||q||)
__device__ uint32_t g_U8[K_ * D_ / 4];   // 32 MB e4m3(16 * u/||u||)

// ---------------- PTX helpers ----------------
__device__ __forceinline__ uint32_t smem_u32(const void* p) {
    uint32_t a;
    asm("{ .reg .u64 t; cvta.to.shared.u64 t, %1; cvt.u32.u64 %0, t; }" : "=r"(a) : "l"(p));
    return a;
}

#define CP_ASYNC16(dst, src) \
    asm volatile("cp.async.cg.shared.global [%0], [%1], 16;\n" :: "r"(dst), "l"(src))
#define CP_COMMIT() asm volatile("cp.async.commit_group;\n" ::: "memory")
#define CP_WAIT(n)  asm volatile("cp.async.wait_group %0;\n" :: "n"(n) : "memory")

#define LDSM4(R0, R1, R2, R3, addr) \
    asm volatile("ldmatrix.sync.aligned.m8n8.x4.shared.b16 {%0,%1,%2,%3}, [%4];" \
        : "=r"(R0), "=r"(R1), "=r"(R2), "=r"(R3) : "r"(addr))

// fp8 e4m3 MMA, fp16 accumulate: D = 2 x .f16x2 regs (halves reg pressure,
// and fp16-acc legacy fp8 mma runs at 2x the fp32-acc rate).
#define MMAFP8H(D, A, B0, B1) \
    asm volatile("mma.sync.aligned.m16n8k32.row.col.f16.e4m3.e4m3.f16 " \
        "{%0,%1}, {%2,%3,%4,%5}, {%6,%7}, {%0,%1};" \
        : "+r"((D)[0]), "+r"((D)[1]) \
        : "r"((A)[0]), "r"((A)[1]), "r"((A)[2]), "r"((A)[3]), "r"(B0), "r"(B1))

__device__ __forceinline__ float warp_sum(float v) {
#pragma unroll
    for (int o = 16; o > 0; o >>= 1) v += __shfl_xor_sync(0xffffffffu, v, o);
    return v;
}

__device__ __forceinline__ uint32_t pack_e4m3x4(float e0, float e1, float e2, float e3) {
    uint16_t lo, hi;
    asm("cvt.rn.satfinite.e4m3x2.f32 %0, %1, %2;" : "=h"(lo) : "f"(e1), "f"(e0));
    asm("cvt.rn.satfinite.e4m3x2.f32 %0, %1, %2;" : "=h"(hi) : "f"(e3), "f"(e2));
    return (uint32_t)lo | ((uint32_t)hi << 16);
}

// ---------------------------------------------------------------------------
// Merged prep: blocks [0,N_) = query/keys; blocks [N_, N_+K_) = queue.
// ---------------------------------------------------------------------------
__global__ void prep(const float* __restrict__ q, const float* __restrict__ k,
                     const float* __restrict__ u) {
    int tid = threadIdx.x;  // 128
    int wid = tid >> 5, lid = tid & 31;

    if ((int)blockIdx.x < N_) {
        int n = blockIdx.x;
        if (n == 0 && tid == 0) g_cnt = 0;
        float4 a = ((const float4*)(q + (size_t)n * D_))[tid];
        float4 b = ((const float4*)(k + (size_t)n * D_))[tid];
        float sq = a.x * a.x + a.y * a.y + a.z * a.z + a.w * a.w;
        float sk = b.x * b.x + b.y * b.y + b.z * b.z + b.w * b.w;
        float dp = a.x * b.x + a.y * b.y + a.z * b.z + a.w * b.w;

        __shared__ float s_sq[4], s_sk[4], s_dp[4];
        __shared__ float s_scale;
        sq = warp_sum(sq); sk = warp_sum(sk); dp = warp_sum(dp);
        if (lid == 0) { s_sq[wid] = sq; s_sk[wid] = sk; s_dp[wid] = dp; }
        __syncthreads();
        if (tid == 0) {
            float tsq = s_sq[0] + s_sq[1] + s_sq[2] + s_sq[3];
            float tsk = s_sk[0] + s_sk[1] + s_sk[2] + s_sk[3];
            float tdp = s_dp[0] + s_dp[1] + s_dp[2] + s_dp[3];
            float qn = sqrtf(tsq), kn = sqrtf(tsk);
            float lpos = tdp / fmaxf(qn * kn, EPS) * TEMP_INV;
            g_lpos[n] = lpos;
            g_S[n] = expf(lpos - CSHIFT);
            s_scale = TEMP_INV * QSCALE / qn;
        }
        __syncthreads();
        float s = s_scale;
        g_Q8[(size_t)n * 128 + tid] = pack_e4m3x4(a.x * s, a.y * s, a.z * s, a.w * s);
    } else {
        int r = blockIdx.x - N_;
        float4 a = ((const float4*)(u + (size_t)r * D_))[tid];
        float s = a.x * a.x + a.y * a.y + a.z * a.z + a.w * a.w;
        __shared__ float sm[4];
        __shared__ float s_scale;
        s = warp_sum(s);
        if (lid == 0) sm[wid] = s;
        __syncthreads();
        if (tid == 0) s_scale = USCALE * rsqrtf(sm[0] + sm[1] + sm[2] + sm[3]);
        __syncthreads();
        float sc = s_scale;
        g_U8[(size_t)r * 128 + tid] = pack_e4m3x4(a.x * sc, a.y * sc, a.z * sc, a.w * sc);
    }
}

// ---------------------------------------------------------------------------
// GEMM+LSE via fp8 mma.m16n8k32 (e4m3 -> f16 acc), 4-stage cp.async pipeline.
// CTA 128(M,queue) x 128(N,query), BK=64, warps 2Mx4N, warp tile 64x32.
// ---------------------------------------------------------------------------
constexpr int BM = 128, BN = 128, BK = 64;
constexpr uint32_t ROWB = 80;
constexpr uint32_t A_BYTES = 128 * ROWB;           // 10240
constexpr uint32_t STAGE_BYTES = 2 * A_BYTES;      // 20480
constexpr int NSTAGE = 4;
constexpr uint32_t SMEM_TOTAL = NSTAGE * STAGE_BYTES;  // 81920
constexpr int NIT = D_ / BK;                       // 8
constexpr int TOTAL_CTAS = (N_ / BN) * (K_ / BM);  // 8192

__global__ __launch_bounds__(256, 2) void gemm_lse_fp8(float* __restrict__ out) {
    extern __shared__ __align__(128) char smem[];
    const uint32_t sb = smem_u32(smem);
    const int tid = threadIdx.x;
    const int wid = tid >> 5, lane = tid & 31;
    const int n0 = blockIdx.x * BN;      // query tile (fast -> U8 shared via L2)
    const int m0 = blockIdx.y * BM;      // queue tile
    const int warp_m = wid & 1;
    const int warp_n = wid >> 1;

    // ---- precompute the 4 cp.async (src ptr, dst offset) pairs ----
    const uint8_t* Q8 = (const uint8_t*)g_Q8;
    const uint8_t* U8 = (const uint8_t*)g_U8;
    const uint8_t* src[4];
    uint32_t dsto[4];
#pragma unroll
    for (int i = 0; i < 4; i++) {
        int id = tid + i * 256;          // 0..1023 : first 512 = A(U8), rest = B(Q8)
        int isB = (id >= 512);
        int l2 = id & 511;
        int row = l2 >> 2, c = l2 & 3;
        src[i] = (isB ? Q8 + (size_t)(n0 + row) * D_ : U8 + (size_t)(m0 + row) * D_)
                 + c * 16;
        dsto[i] = (isB ? A_BYTES : 0u) + row * ROWB + c * 16u;
    }

    uint32_t acc[4][4][2];               // f16x2 accumulators (half the regs)
#pragma unroll
    for (int i = 0; i < 4; i++)
#pragma unroll
        for (int j = 0; j < 4; j++) { acc[i][j][0] = 0u; acc[i][j][1] = 0u; }

    // ---- prologue: fill 3 stages ----
#pragma unroll
    for (int s = 0; s < 3; s++) {
        uint32_t base = sb + s * STAGE_BYTES;
#pragma unroll
        for (int i = 0; i < 4; i++) CP_ASYNC16(base + dsto[i], src[i]);
        CP_COMMIT();
#pragma unroll
        for (int i = 0; i < 4; i++) src[i] += BK;
    }

    const uint32_t aOff = (warp_m * 64 + (lane & 15)) * ROWB + ((lane >> 4) * 16);
    const uint32_t bOff = A_BYTES + (warp_n * 32 + (lane & 15)) * ROWB + ((lane >> 4) * 16);

#pragma unroll
    for (int it = 0; it < NIT; it++) {
        if (it < NIT - 2)      { CP_WAIT(2); }
        else if (it == NIT - 2){ CP_WAIT(1); }
        else                   { CP_WAIT(0); }
        __syncthreads();
        if (it + 3 < NIT) {
            uint32_t base = sb + ((it + 3) & 3) * STAGE_BYTES;
#pragma unroll
            for (int i = 0; i < 4; i++) CP_ASYNC16(base + dsto[i], src[i]);
            CP_COMMIT();
#pragma unroll
            for (int i = 0; i < 4; i++) src[i] += BK;
        }
        const uint32_t stb = sb + (it & 3) * STAGE_BYTES;
#pragma unroll
        for (int ks = 0; ks < 2; ks++) {
            uint32_t a[4][4], b[2][4];
#pragma unroll
            for (int mt = 0; mt < 4; mt++)
                LDSM4(a[mt][0], a[mt][1], a[mt][2], a[mt][3],
                      stb + aOff + mt * 16 * ROWB + ks * 32);
#pragma unroll
            for (int ng = 0; ng < 2; ng++)
                LDSM4(b[ng][0], b[ng][1], b[ng][2], b[ng][3],
                      stb + bOff + ng * 16 * ROWB + ks * 32);
#pragma unroll
            for (int mt = 0; mt < 4; mt++) {
#pragma unroll
                for (int ng = 0; ng < 2; ng++) {
                    MMAFP8H(acc[mt][2 * ng + 0], a[mt], b[ng][0], b[ng][2]);
                    MMAFP8H(acc[mt][2 * ng + 1], a[mt], b[ng][1], b[ng][3]);
                }
            }
        }
    }

    // Epilogue: logit = acc/256; exp(l-5); reduce over 64 warp rows; atomics.
    // f16 frag: reg0 = {(r,c),(r,c+1)}, reg1 = {(r+8,c),(r+8,c+1)}
#pragma unroll
    for (int j = 0; j < 4; j++) {
        float s0 = 0.0f, s1 = 0.0f;
#pragma unroll
        for (int mt = 0; mt < 4; mt++) {
            float2 f0 = __half22float2(*(const __half2*)&acc[mt][j][0]);
            float2 f1 = __half22float2(*(const __half2*)&acc[mt][j][1]);
            s0 += __expf(fmaf(f0.x, INV_SCALE, -CSHIFT))
                + __expf(fmaf(f1.x, INV_SCALE, -CSHIFT));
            s1 += __expf(fmaf(f0.y, INV_SCALE, -CSHIFT))
                + __expf(fmaf(f1.y, INV_SCALE, -CSHIFT));
        }
#pragma unroll
        for (int o = 4; o <= 16; o <<= 1) {
            s0 += __shfl_xor_sync(0xffffffffu, s0, o);
            s1 += __shfl_xor_sync(0xffffffffu, s1, o);
        }
        if (lane < 4) {
            int col = n0 + warp_n * 32 + j * 8 + lane * 2;
            atomicAdd(&g_S[col], s0);
            atomicAdd(&g_S[col + 1], s1);
        }
    }

    // Fused finalize: last CTA computes the loss.
    __shared__ bool s_last;
    __threadfence();
    __syncthreads();
    if (tid == 0) s_last = (atomicAdd(&g_cnt, 1u) == TOTAL_CTAS - 1);
    __syncthreads();
    if (s_last) {
        float local = 0.0f;
        for (int n = tid; n < N_; n += 256)
            local += CSHIFT + logf(__ldcg(&g_S[n])) - g_lpos[n];
        __shared__ float red[256];
        red[tid] = local;
        __syncthreads();
        for (int s = 128; s > 0; s >>= 1) {
            if (tid < s) red[tid] += red[tid + s];
            __syncthreads();
        }
        if (tid == 0) out[0] = red[0] / (float)N_;
    }
}

extern "C" void kernel_launch(void* const* d_in, const int* in_sizes, int n_in,
                              void* d_out, int out_size) {
    const float* query = (const float*)d_in[0];
    const float* keys  = (const float*)d_in[1];
    const float* queue = (const float*)d_in[2];
    float* out = (float*)d_out;

    cudaFuncSetAttribute(gemm_lse_fp8, cudaFuncAttributeMaxDynamicSharedMemorySize, SMEM_TOTAL);

    prep<<<N_ + K_, 128>>>(query, keys, queue);
    dim3 grid(N_ / BN, K_ / BM);   // 16 x 512, x fast -> U8 tiles shared in L2
    gemm_lse_fp8<<<grid, 256, SMEM_TOTAL>>>(out);
}